// round 14
// baseline (speedup 1.0000x reference)
#include <cuda_runtime.h>
#include <cstdint>

// ---------------------------------------------------------------------------
// SplitPool, round 13: 2-launch pipeline with PDL; pool rewritten to a
// cp.async.bulk (TMA bulk engine) double-buffered smem pipeline to bypass
// the per-SM L1tex miss-tracking cap that four LDG-based variants plateaued
// at (~5.3 TB/s).
//   1. setup_kernel : zero d_out + chunk metadata (scan/dest/inv), PDL-trigger.
//   2. pool_kernel  : per block: contiguous row region, 32-row (16KB) stages
//                     bulk-copied gmem->smem (mbarrier complete_tx), consumed
//                     by 8 warps (4 rows each) with R10-style monotone chunk
//                     advance + pre-scaled atomicAdd into d_out.
// ---------------------------------------------------------------------------

#define DIM 128
#define DIM4 (DIM / 4)
#define MAX_CHUNKS 8192
#define MAX_B 64
#define THREADS 256
#define BLOCKS_PER_SM 4
#define STAGE_ROWS 32
#define STAGE_FLOATS (STAGE_ROWS * DIM)
#define STAGE_BYTES (STAGE_FLOATS * 4)

__device__ int   g_cs[MAX_CHUNKS + 2];   // exclusive row offsets (chunk starts)
__device__ int   g_dest[MAX_CHUNKS + 1]; // output float offset, -1 = dropped
__device__ float g_inv[MAX_CHUNKS];      // 1 / max(count, 1)

// ---- PTX helpers -----------------------------------------------------------
__device__ __forceinline__ uint32_t smem_u32(const void* p) {
    uint32_t a;
    asm("{ .reg .u64 t; cvta.to.shared.u64 t, %1; cvt.u32.u64 %0, t; }"
        : "=r"(a) : "l"(p));
    return a;
}
#define MBAR_INIT(mb, cnt) \
    asm volatile("mbarrier.init.shared.b64 [%0], %1;" :: "r"(mb), "r"(cnt) : "memory")
#define MBAR_EXPECT_TX(mb, bytes) \
    asm volatile("mbarrier.arrive.expect_tx.shared.b64 _, [%0], %1;" \
                 :: "r"(mb), "r"(bytes) : "memory")
#define BULK_G2S(dst, src, bytes, mb) \
    asm volatile("cp.async.bulk.shared::cta.global.mbarrier::complete_tx::bytes " \
                 "[%0], [%1], %2, [%3];" \
                 :: "r"(dst), "l"(src), "r"(bytes), "r"(mb) : "memory")
#define FENCE_PROXY_ASYNC() \
    asm volatile("fence.proxy.async.shared::cta;" ::: "memory")

__device__ __forceinline__ void mbar_wait(uint32_t mb, uint32_t parity) {
    asm volatile(
        "{\n\t.reg .pred P;\n\t"
        "WAIT_%=:\n\t"
        "mbarrier.try_wait.parity.acquire.cta.shared::cta.b64 P, [%0], %1, 0x989680;\n\t"
        "@P bra.uni DONE_%=;\n\t"
        "bra.uni WAIT_%=;\n\t"
        "DONE_%=:\n\t}"
        :: "r"(mb), "r"(parity) : "memory");
}

// ---------------------------------------------------------------------------
// Kernel 1: setup. Block 0: scan + chunk metadata. Blocks >=1: zero output.
// ---------------------------------------------------------------------------
__global__ __launch_bounds__(1024) void setup_kernel(
    const int* __restrict__ cs, int n_chunks,
    const int* __restrict__ np, int B, int P,
    float* __restrict__ out, int out_f4) {

    if (blockIdx.x > 0) {
        float4* o4 = reinterpret_cast<float4*>(out);
        const float4 z = make_float4(0.f, 0.f, 0.f, 0.f);
        for (int i = (blockIdx.x - 1) * blockDim.x + threadIdx.x; i < out_f4;
             i += (gridDim.x - 1) * blockDim.x)
            o4[i] = z;
        cudaTriggerProgrammaticLaunchCompletion();
        return;
    }

    __shared__ int warp_pref[32];
    __shared__ int s_pool[MAX_B + 1];
    __shared__ int s_np[MAX_B];

    const int t = threadIdx.x;
    const int lane = t & 31;
    const int w = t >> 5;
    const int per = (n_chunks + 1023) >> 10;

    int v[8];
    int tot = 0;
    #pragma unroll
    for (int k = 0; k < 8; k++) {
        int idx = t * per + k;
        int val = (k < per && idx < n_chunks) ? cs[idx] : 0;
        v[k] = val;
        tot += val;
    }

    int inc = tot;
    #pragma unroll
    for (int off = 1; off < 32; off <<= 1) {
        int n = __shfl_up_sync(0xffffffffu, inc, off);
        if (lane >= off) inc += n;
    }
    if (lane == 31) warp_pref[w] = inc;
    if (t < B) s_np[t] = np[t];
    __syncthreads();

    if (w == 0) {
        int ws = warp_pref[lane];
        #pragma unroll
        for (int off = 1; off < 32; off <<= 1) {
            int n = __shfl_up_sync(0xffffffffu, ws, off);
            if (lane >= off) ws += n;
        }
        warp_pref[lane] = ws;
    }
    __syncthreads();

    int pref = inc - tot + (w > 0 ? warp_pref[w - 1] : 0);
    #pragma unroll
    for (int k = 0; k < 8; k++) {
        int idx = t * per + k;
        if (k < per && idx < n_chunks) {
            g_cs[idx] = pref;
            pref += v[k];
        }
    }
    if (t == 1023) {
        g_cs[n_chunks] = warp_pref[31];
        g_cs[n_chunks + 1] = 0x7fffffff;   // sentinel
    }

    if (t == 0) {
        int acc = 0;
        for (int i = 0; i < B; i++) { s_pool[i] = acc; acc += s_np[i] + 1; }
        s_pool[B] = acc;
        g_dest[n_chunks] = -1;             // safe target for trailing flush
    }
    __syncthreads();

    #pragma unroll
    for (int k = 0; k < 8; k++) {
        int c = t * per + k;
        if (k >= per || c >= n_chunks) break;
        int i = 0;
        while (i < B - 1 && s_pool[i + 1] <= c) i++;
        int peak = c - s_pool[i];
        bool valid = peak < s_np[i];
        g_dest[c] = valid ? (i * P + peak) * DIM : -1;
        g_inv[c]  = 1.0f / (float)max(v[k], 1);
    }
    cudaTriggerProgrammaticLaunchCompletion();
}

// ---------------------------------------------------------------------------
// Kernel 2: bulk-copy double-buffered segment reduction.
// ---------------------------------------------------------------------------
__global__ __launch_bounds__(THREADS, BLOCKS_PER_SM)
void pool_kernel(const float* __restrict__ x, float* __restrict__ out,
                 int n_chunks, int total_rows, int rpb) {
    __shared__ __align__(128) float buf[2][STAGE_FLOATS];
    __shared__ __align__(8) unsigned long long mbar[2];

    const int t = threadIdx.x;
    const int lane = t & 31;
    const int w = t >> 5;

    const int r0 = blockIdx.x * rpb;
    const int r_end = min(r0 + rpb, total_rows);
    const int nst = (r_end > r0) ? (r_end - r0 + STAGE_ROWS - 1) / STAGE_ROWS : 0;

    const uint32_t mb0 = smem_u32(&mbar[0]);
    const uint32_t mb1 = smem_u32(&mbar[1]);
    const uint32_t bf0 = smem_u32(&buf[0][0]);
    const uint32_t bf1 = smem_u32(&buf[1][0]);

    if (t == 0) { MBAR_INIT(mb0, 1); MBAR_INIT(mb1, 1); }
    __syncthreads();

    // issue stage k into buffer k&1 (tid 0 only)
    auto issue = [&](int k) {
        const int b = k & 1;
        const int srow = r0 + k * STAGE_ROWS;
        const uint32_t bytes = (uint32_t)(min(STAGE_ROWS, r_end - srow) * DIM * 4);
        const uint32_t mb = b ? mb1 : mb0;
        MBAR_EXPECT_TX(mb, bytes);
        BULK_G2S(b ? bf1 : bf0, x + (size_t)srow * DIM, bytes, mb);
    };

    // warm the pipeline before waiting on setup (x is a pure input)
    if (t == 0 && nst > 0) {
        issue(0);
        if (nst > 1) issue(1);
    }

    cudaGridDependencySynchronize();  // setup's g_cs/g_dest/g_inv + zeroed out
    if (nst == 0) return;

    // binary search: largest chunk c with g_cs[c] <= first owned row
    const int myrow0 = min(r0 + w * 4, total_rows - 1);
    int lo = 0, hi = n_chunks - 1;
    while (lo < hi) {
        int mid = (lo + hi + 1) >> 1;
        if (__ldg(&g_cs[mid]) <= myrow0) lo = mid; else hi = mid - 1;
    }
    int c = lo;
    int cend = __ldg(&g_cs[c + 1]);

    float4 acc = make_float4(0.f, 0.f, 0.f, 0.f);

    auto flush = [&]() {
        const int dest = __ldg(&g_dest[c]);
        if (dest >= 0) {
            const float inv = __ldg(&g_inv[c]);
            float* o = out + dest + lane * 4;
            atomicAdd(o + 0, acc.x * inv);
            atomicAdd(o + 1, acc.y * inv);
            atomicAdd(o + 2, acc.z * inv);
            atomicAdd(o + 3, acc.w * inv);
        }
        acc = make_float4(0.f, 0.f, 0.f, 0.f);
    };

    int ph0 = 0, ph1 = 0;

    for (int k = 0; k < nst; k++) {
        const int b = k & 1;
        if (b) { mbar_wait(mb1, ph1); ph1 ^= 1; }
        else   { mbar_wait(mb0, ph0); ph0 ^= 1; }

        const int srow = r0 + k * STAGE_ROWS;
        const int wrow = srow + w * 4;
        const float* bb = b ? buf[1] : buf[0];

        #pragma unroll
        for (int j = 0; j < 4; j++) {
            const int r = wrow + j;
            if (r < r_end) {
                float4 v = *reinterpret_cast<const float4*>(
                    bb + (r - srow) * DIM + lane * 4);
                if (r >= cend) {                       // row starts next chunk
                    flush();
                    do { c++; cend = __ldg(&g_cs[c + 1]); } while (cend <= r);
                }
                acc.x += v.x; acc.y += v.y; acc.z += v.z; acc.w += v.w;
            }
        }

        __syncthreads();               // all consumed buffer b -> reusable
        if (t == 0 && k + 2 < nst) {
            FENCE_PROXY_ASYNC();       // order generic reads before async write
            issue(k + 2);
        }
    }

    flush();  // trailing partial (g_dest sentinel guards invalid c)
}

// ---------------------------------------------------------------------------
// Launch: setup, then pool with PDL dependency.
// ---------------------------------------------------------------------------
extern "C" void kernel_launch(void* const* d_in, const int* in_sizes, int n_in,
                              void* d_out, int out_size) {
    const float* x       = (const float*)d_in[0];
    const int*   cs      = (const int*)d_in[1];
    const int*   n_peaks = (const int*)d_in[2];

    const int n_chunks   = in_sizes[1];
    const int B          = in_sizes[2];
    const int total_rows = in_sizes[0] / DIM;
    const int P          = out_size / (B * DIM);   // max_n_peaks

    // 1. setup
    setup_kernel<<<65, 1024>>>(cs, n_chunks, n_peaks, B, P,
                               (float*)d_out, out_size / 4);

    // 2. pool: single wave, contiguous region per block, multiple of STAGE_ROWS
    int sms = 148, dev = 0;
    cudaGetDevice(&dev);
    cudaDeviceGetAttribute(&sms, cudaDevAttrMultiProcessorCount, dev);
    const int nblk = sms * BLOCKS_PER_SM;
    const int rpb = ((total_rows + nblk - 1) / nblk + STAGE_ROWS - 1)
                    / STAGE_ROWS * STAGE_ROWS;

    cudaLaunchConfig_t cfg = {};
    cfg.gridDim  = dim3(nblk, 1, 1);
    cfg.blockDim = dim3(THREADS, 1, 1);
    cfg.dynamicSmemBytes = 0;
    cfg.stream = 0;
    cudaLaunchAttribute attrs[1];
    attrs[0].id = cudaLaunchAttributeProgrammaticStreamSerialization;
    attrs[0].val.programmaticStreamSerializationAllowed = 1;
    cfg.attrs = attrs;
    cfg.numAttrs = 1;

    cudaError_t e = cudaLaunchKernelEx(&cfg, pool_kernel,
                                       x, (float*)d_out, n_chunks,
                                       total_rows, rpb);
    if (e != cudaSuccess) {
        pool_kernel<<<nblk, THREADS>>>(x, (float*)d_out, n_chunks,
                                       total_rows, rpb);
    }
}